// round 1
// baseline (speedup 1.0000x reference)
#include <cuda_runtime.h>
#include <cstdint>

#define NBATCH 512
#define TSTEPS 128
#define NS 32
#define NC 16
#define NSC 48

// scratch for gains (layout [t][b][c][s] / [t][b][c])
__device__ float g_K[(size_t)TSTEPS * NBATCH * NC * NS];
__device__ float g_k[(size_t)TSTEPS * NBATCH * NC];

// ---------------------------------------------------------------------------
// Backward Riccati pass. One CTA per batch, 256 threads (8 warps).
// ---------------------------------------------------------------------------
__global__ __launch_bounds__(256, 4)
void lqr_bwd_kernel(const float* __restrict__ Q,
                    const float* __restrict__ p,
                    const float* __restrict__ A,
                    const float* __restrict__ Bm,
                    const float* __restrict__ c1)
{
    __shared__ float Fs[NS][NSC + 1];     // F[k][j] (k state row, j col: [A | Bm])
    __shared__ float Ws[NS][NSC + 1];     // W = V * F
    __shared__ float Qts[NSC][NSC + 1];   // Qt = Q[t] + F^T V F
    __shared__ float Qinv[NC][NC + 1];    // Quu^{-1}
    __shared__ float Ks[NC][NS + 1];      // K_t
    __shared__ float kts[NC];             // k_t
    __shared__ float vs[NS];              // v
    __shared__ float w2[NS];              // v + V c1
    __shared__ float qts[NSC];            // q_t
    __shared__ float c1s[NS];

    const int b = blockIdx.x;
    const int tid = threadIdx.x;
    const int lane = tid & 31;
    const int wid = tid >> 5;

    // Load F = [A | Bm]
    for (int o = tid; o < NS * NSC; o += 256) {
        int k = o / NSC, j = o % NSC;
        Fs[k][j] = (j < NS) ? A[b * NS * NS + k * NS + j]
                            : Bm[b * NS * NC + k * NC + (j - NS)];
    }
    if (tid < NS) { c1s[tid] = c1[b * NS + tid]; vs[tid] = 0.f; }
    __syncthreads();

    // Register-resident state:
    // vreg[r] = V[4*wid + r][lane]   (V symmetric, init 0)
    float vreg[4] = {0.f, 0.f, 0.f, 0.f};
    // fb[r] = F[lane][6*wid + r]  (column strip of F used in phase B, constant over t)
    float fb[6];
#pragma unroll
    for (int r = 0; r < 6; ++r) fb[r] = Fs[lane][6 * wid + r];

    for (int t = TSTEPS - 1; t >= 0; --t) {
        const float* Qg = Q + ((size_t)(b * TSTEPS + t)) * (NSC * NSC);
        const float* pg = p + ((size_t)(b * TSTEPS + t)) * NSC;

        // ---------------- Phase A: W = V * F ----------------
        // warp w -> rows 4w..4w+3 ; lane -> col lane (+ col 32+lane for lane<16)
        {
            float acc0[4] = {0.f, 0.f, 0.f, 0.f};
            float acc1[4] = {0.f, 0.f, 0.f, 0.f};
#pragma unroll
            for (int k = 0; k < NS; ++k) {
                float f0 = Fs[k][lane];
                float f1 = (lane < 16) ? Fs[k][32 + lane] : 0.f;
#pragma unroll
                for (int r = 0; r < 4; ++r) {
                    float vik = __shfl_sync(0xffffffffu, vreg[r], k);
                    acc0[r] = fmaf(vik, f0, acc0[r]);
                    acc1[r] = fmaf(vik, f1, acc1[r]);
                }
            }
#pragma unroll
            for (int r = 0; r < 4; ++r) {
                Ws[4 * wid + r][lane] = acc0[r];
                if (lane < 16) Ws[4 * wid + r][32 + lane] = acc1[r];
            }
        }
        // w2 = v + V * c1  (warp-reduce over lanes of vreg)
        {
#pragma unroll
            for (int r = 0; r < 4; ++r) {
                float t0 = vreg[r] * c1s[lane];
#pragma unroll
                for (int s = 16; s; s >>= 1) t0 += __shfl_xor_sync(0xffffffffu, t0, s);
                if (lane == 0) w2[4 * wid + r] = vs[4 * wid + r] + t0;
            }
        }
        __syncthreads();

        // ---------------- Phase B: Qt = Q[t] + F^T W ; qt = p[t] + F^T w2 ----
        // warp w -> rows 6w..6w+5 ; lane -> col lane (+ col 32+lane for lane<16)
        {
            float acc0[6], acc1[6];
#pragma unroll
            for (int r = 0; r < 6; ++r) {
                int i = 6 * wid + r;
                acc0[r] = Qg[i * NSC + lane];
                acc1[r] = (lane < 16) ? Qg[i * NSC + 32 + lane] : 0.f;
            }
#pragma unroll
            for (int k = 0; k < NS; ++k) {
                float m0 = Ws[k][lane];
                float m1 = (lane < 16) ? Ws[k][32 + lane] : 0.f;
#pragma unroll
                for (int r = 0; r < 6; ++r) {
                    float fki = __shfl_sync(0xffffffffu, fb[r], k);
                    acc0[r] = fmaf(fki, m0, acc0[r]);
                    acc1[r] = fmaf(fki, m1, acc1[r]);
                }
            }
#pragma unroll
            for (int r = 0; r < 6; ++r) {
                Qts[6 * wid + r][lane] = acc0[r];
                if (lane < 16) Qts[6 * wid + r][32 + lane] = acc1[r];
            }
        }
        if (tid < NSC) {
            float acc = pg[tid];
#pragma unroll
            for (int k = 0; k < NS; ++k) acc = fmaf(Fs[k][tid], w2[k], acc);
            qts[tid] = acc;
        }
        __syncthreads();

        // ---------------- Phase C: Quu^{-1} (warp 0, Gauss-Jordan in registers) --
        if (wid == 0) {
            const int col = lane & 15;
            float a[16];
#pragma unroll
            for (int i = 0; i < 16; ++i) a[i] = Qts[32 + i][32 + col];
#pragma unroll
            for (int pv = 0; pv < 16; ++pv) {
                float piv = __shfl_sync(0xffffffffu, a[pv], pv);
                float pinv = __frcp_rn(piv);
                float cp[16];
#pragma unroll
                for (int i = 0; i < 16; ++i) cp[i] = __shfl_sync(0xffffffffu, a[i], pv);
                float rp = a[pv] * pinv;
#pragma unroll
                for (int i = 0; i < 16; ++i)
                    if (i != pv) a[i] = fmaf(-cp[i], rp, a[i]);
                a[pv] = rp;
                if (lane == pv) {
#pragma unroll
                    for (int i = 0; i < 16; ++i) a[i] = (i == pv) ? pinv : -cp[i] * pinv;
                }
            }
            if (lane < 16) {
#pragma unroll
                for (int i = 0; i < 16; ++i) Qinv[i][lane] = a[i];
            }
        }
        __syncthreads();

        // ---------------- Phase D1: K = -Quu^{-1} Qux ; k = -Quu^{-1} qu ------
        // warp w -> rows 2w, 2w+1 ; lane -> col lane
        {
            float acc[2] = {0.f, 0.f};
            float acck[2] = {0.f, 0.f};
#pragma unroll
            for (int k = 0; k < 16; ++k) {
                float qi0 = Qinv[2 * wid][k];
                float qi1 = Qinv[2 * wid + 1][k];
                float qx = Qts[32 + k][lane];   // Qux[k][lane]
                acc[0] = fmaf(qi0, qx, acc[0]);
                acc[1] = fmaf(qi1, qx, acc[1]);
                float quk = qts[32 + k];
                acck[0] = fmaf(qi0, quk, acck[0]);
                acck[1] = fmaf(qi1, quk, acck[1]);
            }
#pragma unroll
            for (int r = 0; r < 2; ++r) {
                int row = 2 * wid + r;
                float kv = -acc[r];
                Ks[row][lane] = kv;
                g_K[(((size_t)t * NBATCH + b) * NC + row) * NS + lane] = kv;
            }
            if (lane == 0) {
#pragma unroll
                for (int r = 0; r < 2; ++r) {
                    int row = 2 * wid + r;
                    float kv = -acck[r];
                    kts[row] = kv;
                    g_k[((size_t)t * NBATCH + b) * NC + row] = kv;
                }
            }
        }
        __syncthreads();

        // ---------------- Phase D2: V' = Qxx + Qxu K ; v' = qx + Qxu k --------
        {
            float nv[4];
#pragma unroll
            for (int r = 0; r < 4; ++r) nv[r] = Qts[4 * wid + r][lane];
#pragma unroll
            for (int k = 0; k < 16; ++k) {
                float kk = Ks[k][lane];
#pragma unroll
                for (int r = 0; r < 4; ++r)
                    nv[r] = fmaf(Qts[4 * wid + r][32 + k], kk, nv[r]);
            }
#pragma unroll
            for (int r = 0; r < 4; ++r) vreg[r] = nv[r];
        }
        if (wid == 0) {  // v' (32 outputs)
            float nv2 = qts[lane];
#pragma unroll
            for (int k = 0; k < 16; ++k) nv2 = fmaf(Qts[lane][32 + k], kts[k], nv2);
            vs[lane] = nv2;
        }
        __syncthreads();
    }
}

// ---------------------------------------------------------------------------
// Forward rollout + cost. One CTA per batch, 256 threads.
// ---------------------------------------------------------------------------
__global__ __launch_bounds__(256, 4)
void lqr_fwd_kernel(const float* __restrict__ Q,
                    const float* __restrict__ p,
                    const float* __restrict__ A,
                    const float* __restrict__ Bm,
                    const float* __restrict__ c1,
                    const float* __restrict__ x_init,
                    float* __restrict__ out)
{
    __shared__ float As[NS][NS + 1];
    __shared__ float Bs[NS][NC + 1];
    __shared__ float c1s[NS];
    __shared__ float xu[NSC];
    __shared__ float xn[NS];
    __shared__ float Ksh[NC][NS + 1];
    __shared__ float ksh[NC];
    __shared__ float red[8];

    const int b = blockIdx.x;
    const int tid = threadIdx.x;

    const size_t xBase = 0;
    const size_t uBase = (size_t)NBATCH * TSTEPS * NS;
    const size_t cBase = uBase + (size_t)NBATCH * TSTEPS * NC;

    for (int o = tid; o < NS * NS; o += 256) As[o / NS][o % NS] = A[b * NS * NS + o];
    for (int o = tid; o < NS * NC; o += 256) Bs[o / NC][o % NC] = Bm[b * NS * NC + o];
    if (tid < NS) { c1s[tid] = c1[b * NS + tid]; xu[tid] = x_init[b * NS + tid]; }
    __syncthreads();

    float cacc = 0.f;

    for (int t = 0; t < TSTEPS; ++t) {
        const float* Qg = Q + ((size_t)(b * TSTEPS + t)) * (NSC * NSC);
        const float* pg = p + ((size_t)(b * TSTEPS + t)) * NSC;
        const float* Kg = g_K + ((size_t)t * NBATCH + b) * (NC * NS);

        for (int o = tid; o < NC * NS; o += 256) Ksh[o / NS][o % NS] = Kg[o];
        if (tid < NC) ksh[tid] = g_k[((size_t)t * NBATCH + b) * NC + tid];
        __syncthreads();

        // u = K x + k ; also write x_t out
        if (tid < NC) {
            float acc = ksh[tid];
#pragma unroll
            for (int s = 0; s < NS; ++s) acc = fmaf(Ksh[tid][s], xu[s], acc);
            xu[NS + tid] = acc;
            out[uBase + (size_t)(b * TSTEPS + t) * NC + tid] = acc;
        }
        if (tid >= 32 && tid < 64) {
            int s = tid - 32;
            out[xBase + (size_t)(b * TSTEPS + t) * NS + s] = xu[s];
        }
        __syncthreads();

        // cost partial: 0.5 * xu^T Q xu + p . xu (each thread 9 Q elements)
        {
            float part = 0.f;
#pragma unroll
            for (int r = 0; r < 9; ++r) {
                int o = tid + 256 * r;
                part = fmaf(Qg[o], xu[o / NSC] * xu[o % NSC], part);
            }
            float pterm = (tid < NSC) ? pg[tid] * xu[tid] : 0.f;
            cacc += 0.5f * part + pterm;
        }
        // x_next = A x + Bm u + c1
        if (tid < NS) {
            float acc = c1s[tid];
#pragma unroll
            for (int k = 0; k < NS; ++k) acc = fmaf(As[tid][k], xu[k], acc);
#pragma unroll
            for (int k = 0; k < NC; ++k) acc = fmaf(Bs[tid][k], xu[NS + k], acc);
            xn[tid] = acc;
        }
        __syncthreads();
        if (tid < NS) xu[tid] = xn[tid];
        __syncthreads();
    }

    // block-reduce cost
#pragma unroll
    for (int s = 16; s; s >>= 1) cacc += __shfl_xor_sync(0xffffffffu, cacc, s);
    if ((tid & 31) == 0) red[tid >> 5] = cacc;
    __syncthreads();
    if (tid == 0) {
        float tot = 0.f;
#pragma unroll
        for (int i = 0; i < 8; ++i) tot += red[i];
        out[cBase + b] = tot;
    }
}

// ---------------------------------------------------------------------------
extern "C" void kernel_launch(void* const* d_in, const int* in_sizes, int n_in,
                              void* d_out, int out_size)
{
    const float* x_init = (const float*)d_in[0];
    const float* Q      = (const float*)d_in[1];
    const float* p      = (const float*)d_in[2];
    const float* A      = (const float*)d_in[3];
    const float* Bm     = (const float*)d_in[4];
    const float* c1     = (const float*)d_in[5];
    float* out = (float*)d_out;

    lqr_bwd_kernel<<<NBATCH, 256>>>(Q, p, A, Bm, c1);
    lqr_fwd_kernel<<<NBATCH, 256>>>(Q, p, A, Bm, c1, x_init, out);
}

// round 2
// speedup vs baseline: 1.0011x; 1.0011x over previous
#include <cuda_runtime.h>
#include <cstdint>

#define NBATCH 512
#define TSTEPS 128
#define NS 32
#define NC 16
#define NSC 48

// scratch for gains (layout [t][b][c][s] / [t][b][c])
__device__ float g_K[(size_t)TSTEPS * NBATCH * NC * NS];
__device__ float g_k[(size_t)TSTEPS * NBATCH * NC];

// ---------------------------------------------------------------------------
// Backward Riccati pass. One CTA per batch, 256 threads (8 warps).
// ---------------------------------------------------------------------------
__global__ __launch_bounds__(256, 4)
void lqr_bwd_kernel(const float* __restrict__ Q,
                    const float* __restrict__ p,
                    const float* __restrict__ A,
                    const float* __restrict__ Bm,
                    const float* __restrict__ c1)
{
    __shared__ float Fs[NS][NSC + 1];     // F[k][j] (k state row, j col: [A | Bm])
    __shared__ float Ws[NS][NSC + 1];     // W = V * F
    __shared__ float Qts[NSC][NSC + 1];   // Qt = Q[t] + F^T V F
    __shared__ float Qinv[NC][NC + 1];    // Quu^{-1}
    __shared__ float Ks[NC][NS + 1];      // K_t
    __shared__ float kts[NC];             // k_t
    __shared__ float vs[NS];              // v
    __shared__ float w2[NS];              // v + V c1
    __shared__ float qts[NSC];            // q_t
    __shared__ float c1s[NS];

    const int b = blockIdx.x;
    const int tid = threadIdx.x;
    const int lane = tid & 31;
    const int wid = tid >> 5;

    // Load F = [A | Bm]
    for (int o = tid; o < NS * NSC; o += 256) {
        int k = o / NSC, j = o % NSC;
        Fs[k][j] = (j < NS) ? A[b * NS * NS + k * NS + j]
                            : Bm[b * NS * NC + k * NC + (j - NS)];
    }
    if (tid < NS) { c1s[tid] = c1[b * NS + tid]; vs[tid] = 0.f; }
    __syncthreads();

    // Register-resident state:
    // vreg[r] = V[4*wid + r][lane]   (V symmetric, init 0)
    float vreg[4] = {0.f, 0.f, 0.f, 0.f};
    // fb[r] = F[lane][6*wid + r]  (column strip of F used in phase B, constant over t)
    float fb[6];
#pragma unroll
    for (int r = 0; r < 6; ++r) fb[r] = Fs[lane][6 * wid + r];

    for (int t = TSTEPS - 1; t >= 0; --t) {
        const float* Qg = Q + ((size_t)(b * TSTEPS + t)) * (NSC * NSC);
        const float* pg = p + ((size_t)(b * TSTEPS + t)) * NSC;

        // ---------------- Phase A: W = V * F ----------------
        // warp w -> rows 4w..4w+3 ; lane -> col lane (+ col 32+lane for lane<16)
        {
            float acc0[4] = {0.f, 0.f, 0.f, 0.f};
            float acc1[4] = {0.f, 0.f, 0.f, 0.f};
#pragma unroll
            for (int k = 0; k < NS; ++k) {
                float f0 = Fs[k][lane];
                float f1 = (lane < 16) ? Fs[k][32 + lane] : 0.f;
#pragma unroll
                for (int r = 0; r < 4; ++r) {
                    float vik = __shfl_sync(0xffffffffu, vreg[r], k);
                    acc0[r] = fmaf(vik, f0, acc0[r]);
                    acc1[r] = fmaf(vik, f1, acc1[r]);
                }
            }
#pragma unroll
            for (int r = 0; r < 4; ++r) {
                Ws[4 * wid + r][lane] = acc0[r];
                if (lane < 16) Ws[4 * wid + r][32 + lane] = acc1[r];
            }
        }
        // w2 = v + V * c1  (warp-reduce over lanes of vreg)
        {
#pragma unroll
            for (int r = 0; r < 4; ++r) {
                float t0 = vreg[r] * c1s[lane];
#pragma unroll
                for (int s = 16; s; s >>= 1) t0 += __shfl_xor_sync(0xffffffffu, t0, s);
                if (lane == 0) w2[4 * wid + r] = vs[4 * wid + r] + t0;
            }
        }
        __syncthreads();

        // ---------------- Phase B: Qt = Q[t] + F^T W ; qt = p[t] + F^T w2 ----
        // warp w -> rows 6w..6w+5 ; lane -> col lane (+ col 32+lane for lane<16)
        {
            float acc0[6], acc1[6];
#pragma unroll
            for (int r = 0; r < 6; ++r) {
                int i = 6 * wid + r;
                acc0[r] = Qg[i * NSC + lane];
                acc1[r] = (lane < 16) ? Qg[i * NSC + 32 + lane] : 0.f;
            }
#pragma unroll
            for (int k = 0; k < NS; ++k) {
                float m0 = Ws[k][lane];
                float m1 = (lane < 16) ? Ws[k][32 + lane] : 0.f;
#pragma unroll
                for (int r = 0; r < 6; ++r) {
                    float fki = __shfl_sync(0xffffffffu, fb[r], k);
                    acc0[r] = fmaf(fki, m0, acc0[r]);
                    acc1[r] = fmaf(fki, m1, acc1[r]);
                }
            }
#pragma unroll
            for (int r = 0; r < 6; ++r) {
                Qts[6 * wid + r][lane] = acc0[r];
                if (lane < 16) Qts[6 * wid + r][32 + lane] = acc1[r];
            }
        }
        if (tid < NSC) {
            float acc = pg[tid];
#pragma unroll
            for (int k = 0; k < NS; ++k) acc = fmaf(Fs[k][tid], w2[k], acc);
            qts[tid] = acc;
        }
        __syncthreads();

        // ---------------- Phase C: Quu^{-1} (warp 0, Gauss-Jordan in registers) --
        if (wid == 0) {
            const int col = lane & 15;
            float a[16];
#pragma unroll
            for (int i = 0; i < 16; ++i) a[i] = Qts[32 + i][32 + col];
#pragma unroll
            for (int pv = 0; pv < 16; ++pv) {
                float piv = __shfl_sync(0xffffffffu, a[pv], pv);
                float pinv = __frcp_rn(piv);
                float cp[16];
#pragma unroll
                for (int i = 0; i < 16; ++i) cp[i] = __shfl_sync(0xffffffffu, a[i], pv);
                float rp = a[pv] * pinv;
#pragma unroll
                for (int i = 0; i < 16; ++i)
                    if (i != pv) a[i] = fmaf(-cp[i], rp, a[i]);
                a[pv] = rp;
                if (lane == pv) {
#pragma unroll
                    for (int i = 0; i < 16; ++i) a[i] = (i == pv) ? pinv : -cp[i] * pinv;
                }
            }
            if (lane < 16) {
#pragma unroll
                for (int i = 0; i < 16; ++i) Qinv[i][lane] = a[i];
            }
        }
        __syncthreads();

        // ---------------- Phase D1: K = -Quu^{-1} Qux ; k = -Quu^{-1} qu ------
        // warp w -> rows 2w, 2w+1 ; lane -> col lane
        {
            float acc[2] = {0.f, 0.f};
            float acck[2] = {0.f, 0.f};
#pragma unroll
            for (int k = 0; k < 16; ++k) {
                float qi0 = Qinv[2 * wid][k];
                float qi1 = Qinv[2 * wid + 1][k];
                float qx = Qts[32 + k][lane];   // Qux[k][lane]
                acc[0] = fmaf(qi0, qx, acc[0]);
                acc[1] = fmaf(qi1, qx, acc[1]);
                float quk = qts[32 + k];
                acck[0] = fmaf(qi0, quk, acck[0]);
                acck[1] = fmaf(qi1, quk, acck[1]);
            }
#pragma unroll
            for (int r = 0; r < 2; ++r) {
                int row = 2 * wid + r;
                float kv = -acc[r];
                Ks[row][lane] = kv;
                g_K[(((size_t)t * NBATCH + b) * NC + row) * NS + lane] = kv;
            }
            if (lane == 0) {
#pragma unroll
                for (int r = 0; r < 2; ++r) {
                    int row = 2 * wid + r;
                    float kv = -acck[r];
                    kts[row] = kv;
                    g_k[((size_t)t * NBATCH + b) * NC + row] = kv;
                }
            }
        }
        __syncthreads();

        // ---------------- Phase D2: V' = Qxx + Qxu K ; v' = qx + Qxu k --------
        {
            float nv[4];
#pragma unroll
            for (int r = 0; r < 4; ++r) nv[r] = Qts[4 * wid + r][lane];
#pragma unroll
            for (int k = 0; k < 16; ++k) {
                float kk = Ks[k][lane];
#pragma unroll
                for (int r = 0; r < 4; ++r)
                    nv[r] = fmaf(Qts[4 * wid + r][32 + k], kk, nv[r]);
            }
#pragma unroll
            for (int r = 0; r < 4; ++r) vreg[r] = nv[r];
        }
        if (wid == 0) {  // v' (32 outputs)
            float nv2 = qts[lane];
#pragma unroll
            for (int k = 0; k < 16; ++k) nv2 = fmaf(Qts[lane][32 + k], kts[k], nv2);
            vs[lane] = nv2;
        }
        __syncthreads();
    }
}

// ---------------------------------------------------------------------------
// Forward rollout + cost. One CTA per batch, 256 threads.
// ---------------------------------------------------------------------------
__global__ __launch_bounds__(256, 4)
void lqr_fwd_kernel(const float* __restrict__ Q,
                    const float* __restrict__ p,
                    const float* __restrict__ A,
                    const float* __restrict__ Bm,
                    const float* __restrict__ c1,
                    const float* __restrict__ x_init,
                    float* __restrict__ out)
{
    __shared__ float As[NS][NS + 1];
    __shared__ float Bs[NS][NC + 1];
    __shared__ float c1s[NS];
    __shared__ float xu[NSC];
    __shared__ float xn[NS];
    __shared__ float Ksh[NC][NS + 1];
    __shared__ float ksh[NC];
    __shared__ float red[8];

    const int b = blockIdx.x;
    const int tid = threadIdx.x;

    const size_t xBase = 0;
    const size_t uBase = (size_t)NBATCH * TSTEPS * NS;
    const size_t cBase = uBase + (size_t)NBATCH * TSTEPS * NC;

    for (int o = tid; o < NS * NS; o += 256) As[o / NS][o % NS] = A[b * NS * NS + o];
    for (int o = tid; o < NS * NC; o += 256) Bs[o / NC][o % NC] = Bm[b * NS * NC + o];
    if (tid < NS) { c1s[tid] = c1[b * NS + tid]; xu[tid] = x_init[b * NS + tid]; }
    __syncthreads();

    float cacc = 0.f;

    for (int t = 0; t < TSTEPS; ++t) {
        const float* Qg = Q + ((size_t)(b * TSTEPS + t)) * (NSC * NSC);
        const float* pg = p + ((size_t)(b * TSTEPS + t)) * NSC;
        const float* Kg = g_K + ((size_t)t * NBATCH + b) * (NC * NS);

        for (int o = tid; o < NC * NS; o += 256) Ksh[o / NS][o % NS] = Kg[o];
        if (tid < NC) ksh[tid] = g_k[((size_t)t * NBATCH + b) * NC + tid];
        __syncthreads();

        // u = K x + k ; also write x_t out
        if (tid < NC) {
            float acc = ksh[tid];
#pragma unroll
            for (int s = 0; s < NS; ++s) acc = fmaf(Ksh[tid][s], xu[s], acc);
            xu[NS + tid] = acc;
            out[uBase + (size_t)(b * TSTEPS + t) * NC + tid] = acc;
        }
        if (tid >= 32 && tid < 64) {
            int s = tid - 32;
            out[xBase + (size_t)(b * TSTEPS + t) * NS + s] = xu[s];
        }
        __syncthreads();

        // cost partial: 0.5 * xu^T Q xu + p . xu (each thread 9 Q elements)
        {
            float part = 0.f;
#pragma unroll
            for (int r = 0; r < 9; ++r) {
                int o = tid + 256 * r;
                part = fmaf(Qg[o], xu[o / NSC] * xu[o % NSC], part);
            }
            float pterm = (tid < NSC) ? pg[tid] * xu[tid] : 0.f;
            cacc += 0.5f * part + pterm;
        }
        // x_next = A x + Bm u + c1
        if (tid < NS) {
            float acc = c1s[tid];
#pragma unroll
            for (int k = 0; k < NS; ++k) acc = fmaf(As[tid][k], xu[k], acc);
#pragma unroll
            for (int k = 0; k < NC; ++k) acc = fmaf(Bs[tid][k], xu[NS + k], acc);
            xn[tid] = acc;
        }
        __syncthreads();
        if (tid < NS) xu[tid] = xn[tid];
        __syncthreads();
    }

    // block-reduce cost
#pragma unroll
    for (int s = 16; s; s >>= 1) cacc += __shfl_xor_sync(0xffffffffu, cacc, s);
    if ((tid & 31) == 0) red[tid >> 5] = cacc;
    __syncthreads();
    if (tid == 0) {
        float tot = 0.f;
#pragma unroll
        for (int i = 0; i < 8; ++i) tot += red[i];
        out[cBase + b] = tot;
    }
}

// ---------------------------------------------------------------------------
extern "C" void kernel_launch(void* const* d_in, const int* in_sizes, int n_in,
                              void* d_out, int out_size)
{
    const float* x_init = (const float*)d_in[0];
    const float* Q      = (const float*)d_in[1];
    const float* p      = (const float*)d_in[2];
    const float* A      = (const float*)d_in[3];
    const float* Bm     = (const float*)d_in[4];
    const float* c1     = (const float*)d_in[5];
    float* out = (float*)d_out;

    lqr_bwd_kernel<<<NBATCH, 256>>>(Q, p, A, Bm, c1);
    lqr_fwd_kernel<<<NBATCH, 256>>>(Q, p, A, Bm, c1, x_init, out);
}

// round 4
// speedup vs baseline: 1.3340x; 1.3325x over previous
#include <cuda_runtime.h>
#include <cstdint>

#define NBATCH 512
#define TSTEPS 128
#define NS 32
#define NC 16
#define NSC 48
typedef unsigned long long u64;

__device__ float g_K[(size_t)TSTEPS * NBATCH * NC * NS];
__device__ float g_k[(size_t)TSTEPS * NBATCH * NC];

__device__ __forceinline__ u64 ffma2(u64 a, u64 b, u64 c) {
    u64 d; asm("fma.rn.f32x2 %0,%1,%2,%3;" : "=l"(d) : "l"(a), "l"(b), "l"(c)); return d;
}
__device__ __forceinline__ float lohi(u64 v) {
    float lo, hi; asm("mov.b64 {%0,%1},%2;" : "=f"(lo), "=f"(hi) : "l"(v)); return lo + hi;
}
__device__ __forceinline__ u64 pklo(float lo) {
    u64 d; asm("mov.b64 %0,{%1,%2};" : "=l"(d) : "f"(lo), "f"(0.0f)); return d;
}
__device__ __forceinline__ u64 ld64(const float* p) { return *reinterpret_cast<const u64*>(p); }
__device__ __forceinline__ void cpa16(void* s, const void* g) {
    unsigned sa = (unsigned)__cvta_generic_to_shared(s);
    asm volatile("cp.async.ca.shared.global [%0], [%1], 16;" :: "r"(sa), "l"(g));
}
__device__ __forceinline__ void cpcommit() { asm volatile("cp.async.commit_group;"); }
__device__ __forceinline__ void cpwait0() { asm volatile("cp.async.wait_group 0;"); }

#define SF 34
#define SQ 50
#define SX 18

// ---------------------------------------------------------------------------
// Backward Riccati pass. One CTA per batch, 256 threads.
// ---------------------------------------------------------------------------
__global__ __launch_bounds__(256, 4)
void lqr_bwd_kernel(const float* __restrict__ Q, const float* __restrict__ p,
                    const float* __restrict__ A, const float* __restrict__ Bm,
                    const float* __restrict__ c1)
{
    __shared__ __align__(16) float FkT[NSC * SF];   // FkT[j][k] = F[k][j]
    __shared__ __align__(16) float WkT[NSC * SF];   // WkT[j][k] = (V F)[k][j]
    __shared__ __align__(16) float Vs[NS * SF];     // V row-major
    __shared__ __align__(16) float Qts[NSC * SQ];   // Qt row-major
    __shared__ __align__(16) float QuxT[NS * SX];   // QuxT[j][u] = Qux[u][j]
    __shared__ __align__(16) float Qinv[NC * SX];
    __shared__ __align__(16) float KT[NS * SX];     // KT[j][r] = K[r][j]
    __shared__ __align__(16) float qts[NSC + 2];
    __shared__ __align__(16) float kts[NC];
    __shared__ __align__(16) float w2[NS];
    __shared__ __align__(16) float vs[NS];
    __shared__ __align__(16) float c1s[NS];

    const int b = blockIdx.x, tid = threadIdx.x;
    const int lane = tid & 31, wid = tid >> 5;
    const int ty = tid >> 4, tx = tid & 15;

    for (int o = tid; o < NS * NSC; o += 256) {
        int j = o >> 5, k = o & 31;
        FkT[j * SF + k] = (j < NS) ? A[b * NS * NS + k * NS + j]
                                   : Bm[b * NS * NC + k * NC + (j - NS)];
    }
    if (tid < NS) { c1s[tid] = c1[b * NS + tid]; vs[tid] = 0.f; }
    for (int o = tid; o < NS * SF; o += 256) Vs[o] = 0.f;
    __syncthreads();

    const float c1l = c1s[lane];
    int qs_off[9], qg_off[9];
#pragma unroll
    for (int r = 0; r < 9; ++r) {
        int o = tid + 256 * r, i = o / NSC, j = o - i * NSC;
        qg_off[r] = o; qs_off[r] = i * SQ + j;
    }

    for (int t = TSTEPS - 1; t >= 0; --t) {
        const float* Qg = Q + ((size_t)(b * TSTEPS + t)) * (NSC * NSC);
        const float* pg = p + ((size_t)(b * TSTEPS + t)) * NSC;

        // --- Phase A: preload Q[t] -> Qts ; W = V*F ; w2 = v + V c1 ---
#pragma unroll
        for (int r = 0; r < 9; ++r) Qts[qs_off[r]] = Qg[qg_off[r]];
        float preg = (tid < NSC) ? pg[tid] : 0.f;
        {
            u64 a00 = 0, a01 = 0, a02 = 0, a10 = 0, a11 = 0, a12 = 0;
            const float* vr0 = &Vs[(2 * ty) * SF];
            const float* vr1 = &Vs[(2 * ty + 1) * SF];
            const float* f0 = &FkT[(3 * tx) * SF];
            const float* f1 = &FkT[(3 * tx + 1) * SF];
            const float* f2 = &FkT[(3 * tx + 2) * SF];
#pragma unroll
            for (int kp = 0; kp < 16; ++kp) {
                u64 fp0 = ld64(f0 + 2 * kp), fp1 = ld64(f1 + 2 * kp), fp2 = ld64(f2 + 2 * kp);
                u64 v0 = ld64(vr0 + 2 * kp), v1 = ld64(vr1 + 2 * kp);
                a00 = ffma2(v0, fp0, a00); a01 = ffma2(v0, fp1, a01); a02 = ffma2(v0, fp2, a02);
                a10 = ffma2(v1, fp0, a10); a11 = ffma2(v1, fp1, a11); a12 = ffma2(v1, fp2, a12);
            }
            WkT[(3 * tx) * SF + 2 * ty] = lohi(a00);
            WkT[(3 * tx + 1) * SF + 2 * ty] = lohi(a01);
            WkT[(3 * tx + 2) * SF + 2 * ty] = lohi(a02);
            WkT[(3 * tx) * SF + 2 * ty + 1] = lohi(a10);
            WkT[(3 * tx + 1) * SF + 2 * ty + 1] = lohi(a11);
            WkT[(3 * tx + 2) * SF + 2 * ty + 1] = lohi(a12);
        }
#pragma unroll
        for (int r = 0; r < 4; ++r) {
            int i = 4 * wid + r;
            float t0 = Vs[i * SF + lane] * c1l;
#pragma unroll
            for (int s = 16; s; s >>= 1) t0 += __shfl_xor_sync(0xffffffffu, t0, s);
            if (lane == 0) w2[i] = vs[i] + t0;
        }
        __syncthreads();

        // --- Phase B: Qt = Q + F^T W ; qt = p + F^T w2 ; QuxT copy ---
        {
            u64 acc[3][3] = {{0,0,0},{0,0,0},{0,0,0}};
            const float* fr0 = &FkT[(3 * ty) * SF];
            const float* fr1 = &FkT[(3 * ty + 1) * SF];
            const float* fr2 = &FkT[(3 * ty + 2) * SF];
            const float* wc0 = &WkT[(3 * tx) * SF];
            const float* wc1 = &WkT[(3 * tx + 1) * SF];
            const float* wc2 = &WkT[(3 * tx + 2) * SF];
#pragma unroll
            for (int kp = 0; kp < 16; ++kp) {
                u64 w0 = ld64(wc0 + 2 * kp), w1 = ld64(wc1 + 2 * kp), wq = ld64(wc2 + 2 * kp);
                u64 fa = ld64(fr0 + 2 * kp), fb = ld64(fr1 + 2 * kp), fc = ld64(fr2 + 2 * kp);
                acc[0][0] = ffma2(fa, w0, acc[0][0]); acc[0][1] = ffma2(fa, w1, acc[0][1]); acc[0][2] = ffma2(fa, wq, acc[0][2]);
                acc[1][0] = ffma2(fb, w0, acc[1][0]); acc[1][1] = ffma2(fb, w1, acc[1][1]); acc[1][2] = ffma2(fb, wq, acc[1][2]);
                acc[2][0] = ffma2(fc, w0, acc[2][0]); acc[2][1] = ffma2(fc, w1, acc[2][1]); acc[2][2] = ffma2(fc, wq, acc[2][2]);
            }
#pragma unroll
            for (int r = 0; r < 3; ++r)
#pragma unroll
                for (int c = 0; c < 3; ++c) {
                    int i = 3 * ty + r, j = 3 * tx + c;
                    float val = Qts[i * SQ + j] + lohi(acc[r][c]);
                    Qts[i * SQ + j] = val;
                    if (i >= NS && j < NS) QuxT[j * SX + (i - NS)] = val;
                }
        }
        if (tid < NSC) {
            u64 acc = 0;
            const float* fr = &FkT[tid * SF];
#pragma unroll
            for (int kp = 0; kp < 16; ++kp) acc = ffma2(ld64(fr + 2 * kp), ld64(&w2[2 * kp]), acc);
            qts[tid] = preg + lohi(acc);
        }
        __syncthreads();

        // --- Phase C: Quu^{-1} via Gauss-Jordan (warp 0) ---
        if (wid == 0) {
            const int col = lane & 15;
            float a[16];
#pragma unroll
            for (int i = 0; i < 16; ++i) a[i] = Qts[(NS + i) * SQ + NS + col];
#pragma unroll
            for (int pv = 0; pv < 16; ++pv) {
                float piv = __shfl_sync(0xffffffffu, a[pv], pv);
                float pinv = __frcp_rn(piv);
                float cp[16];
#pragma unroll
                for (int i = 0; i < 16; ++i) cp[i] = __shfl_sync(0xffffffffu, a[i], pv);
                float rp = a[pv] * pinv;
#pragma unroll
                for (int i = 0; i < 16; ++i) if (i != pv) a[i] = fmaf(-cp[i], rp, a[i]);
                a[pv] = rp;
                if (lane == pv) {
#pragma unroll
                    for (int i = 0; i < 16; ++i) a[i] = (i == pv) ? pinv : -cp[i] * pinv;
                }
            }
            if (lane < 16) {
#pragma unroll
                for (int i = 0; i < 16; ++i) Qinv[i * SX + lane] = a[i];
            }
        }
        __syncthreads();

        // --- Phase D1: K = -Qinv Qux ; k = -Qinv qu ---
        {
            const int r0 = 2 * wid, r1 = r0 + 1;
            u64 aK0 = 0, aK1 = 0, ak0 = 0, ak1 = 0;
            const float* qx = &QuxT[lane * SX];
#pragma unroll
            for (int kp = 0; kp < 8; ++kp) {
                u64 x = ld64(qx + 2 * kp);
                u64 q0 = ld64(&Qinv[r0 * SX + 2 * kp]);
                u64 q1 = ld64(&Qinv[r1 * SX + 2 * kp]);
                u64 qu = ld64(&qts[NS + 2 * kp]);
                aK0 = ffma2(q0, x, aK0); aK1 = ffma2(q1, x, aK1);
                ak0 = ffma2(q0, qu, ak0); ak1 = ffma2(q1, qu, ak1);
            }
            float K0 = -lohi(aK0), K1 = -lohi(aK1);
            KT[lane * SX + r0] = K0; KT[lane * SX + r1] = K1;
            size_t gb = ((size_t)t * NBATCH + b) * NC;
            g_K[(gb + r0) * NS + lane] = K0;
            g_K[(gb + r1) * NS + lane] = K1;
            if (lane == 0) {
                float k0 = -lohi(ak0), k1 = -lohi(ak1);
                kts[r0] = k0; kts[r1] = k1;
                g_k[gb + r0] = k0; g_k[gb + r1] = k1;
            }
        }
        __syncthreads();

        // --- Phase D2: V' = Qxx + Qxu K ; v' = qx + Qxu k ---
        {
            int i0 = 2 * ty, i1 = i0 + 1, j0 = 2 * tx, j1 = j0 + 1;
            u64 a00 = pklo(Qts[i0 * SQ + j0]), a01 = pklo(Qts[i0 * SQ + j1]);
            u64 a10 = pklo(Qts[i1 * SQ + j0]), a11 = pklo(Qts[i1 * SQ + j1]);
            const float* kc0 = &KT[j0 * SX];
            const float* kc1 = &KT[j1 * SX];
            const float* qr0 = &Qts[i0 * SQ + NS];
            const float* qr1 = &Qts[i1 * SQ + NS];
#pragma unroll
            for (int kp = 0; kp < 8; ++kp) {
                u64 k0 = ld64(kc0 + 2 * kp), k1 = ld64(kc1 + 2 * kp);
                u64 x0 = ld64(qr0 + 2 * kp), x1 = ld64(qr1 + 2 * kp);
                a00 = ffma2(x0, k0, a00); a01 = ffma2(x0, k1, a01);
                a10 = ffma2(x1, k0, a10); a11 = ffma2(x1, k1, a11);
            }
            Vs[i0 * SF + j0] = lohi(a00); Vs[i0 * SF + j1] = lohi(a01);
            Vs[i1 * SF + j0] = lohi(a10); Vs[i1 * SF + j1] = lohi(a11);
        }
        if (tid < NS) {
            u64 acc = pklo(qts[tid]);
            const float* qr = &Qts[tid * SQ + NS];
#pragma unroll
            for (int kp = 0; kp < 8; ++kp) acc = ffma2(ld64(qr + 2 * kp), ld64(&kts[2 * kp]), acc);
            vs[tid] = lohi(acc);
        }
        __syncthreads();
    }
}

// ---------------------------------------------------------------------------
// Forward rollout + cost. One CTA per batch, 256 threads, cp.async pipelined.
// ---------------------------------------------------------------------------
__global__ __launch_bounds__(256, 4)
void lqr_fwd_kernel(const float* __restrict__ Q, const float* __restrict__ p,
                    const float* __restrict__ A, const float* __restrict__ Bm,
                    const float* __restrict__ c1, const float* __restrict__ x_init,
                    float* __restrict__ out)
{
    __shared__ __align__(16) float Qsh[2][NSC * NSC];
    __shared__ __align__(16) float Ksh[2][NC * NS];
    __shared__ __align__(16) float psh[2][NSC];
    __shared__ __align__(16) float ksh[2][NC];
    __shared__ float As[NS * 33];
    __shared__ float Bs[NS * 17];
    __shared__ float c1s[NS];
    __shared__ float xu[2][NSC];
    __shared__ float red[8];

    const int b = blockIdx.x, tid = threadIdx.x;
    const size_t uBase = (size_t)NBATCH * TSTEPS * NS;
    const size_t cBase = uBase + (size_t)NBATCH * TSTEPS * NC;

    for (int o = tid; o < NS * NS; o += 256) As[(o >> 5) * 33 + (o & 31)] = A[b * NS * NS + o];
    for (int o = tid; o < NS * NC; o += 256) Bs[(o >> 4) * 17 + (o & 15)] = Bm[b * NS * NC + o];
    if (tid < NS) { c1s[tid] = c1[b * NS + tid]; xu[0][tid] = x_init[b * NS + tid]; }

    // stage t=0
    {
        const float* Qg = Q + ((size_t)b * TSTEPS) * (NSC * NSC);
        const float* Kg = g_K + (size_t)b * NC * NS;
        for (int o = tid; o < 576; o += 256) cpa16(&Qsh[0][4 * o], Qg + 4 * o);
        if (tid < 128) cpa16(&Ksh[0][4 * tid], Kg + 4 * tid);
        if (tid < 12) cpa16(&psh[0][4 * tid], p + ((size_t)b * TSTEPS) * NSC + 4 * tid);
        if (tid < 4) cpa16(&ksh[0][4 * tid], g_k + (size_t)b * NC + 4 * tid);
        cpcommit();
    }
    cpwait0();
    __syncthreads();

    int io[9], jo[9];
#pragma unroll
    for (int r = 0; r < 9; ++r) { int o = tid + 256 * r; io[r] = o / NSC; jo[r] = o - io[r] * NSC; }

    float cacc = 0.f;

    for (int t = 0; t < TSTEPS; ++t) {
        const int cur = t & 1, nxt = cur ^ 1;

        if (t + 1 < TSTEPS) {
            const float* Qg = Q + ((size_t)(b * TSTEPS + t + 1)) * (NSC * NSC);
            const float* Kg = g_K + ((size_t)(t + 1) * NBATCH + b) * NC * NS;
            for (int o = tid; o < 576; o += 256) cpa16(&Qsh[nxt][4 * o], Qg + 4 * o);
            if (tid < 128) cpa16(&Ksh[nxt][4 * tid], Kg + 4 * tid);
            if (tid < 12) cpa16(&psh[nxt][4 * tid], p + ((size_t)(b * TSTEPS + t + 1)) * NSC + 4 * tid);
            if (tid < 4) cpa16(&ksh[nxt][4 * tid], g_k + ((size_t)(t + 1) * NBATCH + b) * NC + 4 * tid);
            cpcommit();
        }

        // u = K x + k (16 threads per output, partial-width shfl reduce)
        {
            int c = tid >> 4, s = tid & 15;
            const float* Kc = &Ksh[cur][c * NS];
            float part = Kc[s] * xu[cur][s] + Kc[16 + s] * xu[cur][16 + s];
#pragma unroll
            for (int m = 8; m; m >>= 1) part += __shfl_xor_sync(0xffffffffu, part, m, 16);
            if (s == 0) {
                float u = part + ksh[cur][c];
                xu[cur][NS + c] = u;
                out[uBase + (size_t)(b * TSTEPS + t) * NC + c] = u;
            }
        }
        if (tid >= 64 && tid < 96)
            out[(size_t)(b * TSTEPS + t) * NS + (tid - 64)] = xu[cur][tid - 64];
        __syncthreads();

        // cost partial
        {
            float part = 0.f;
#pragma unroll
            for (int r = 0; r < 9; ++r)
                part = fmaf(Qsh[cur][tid + 256 * r], xu[cur][io[r]] * xu[cur][jo[r]], part);
            float pterm = (tid < NSC) ? psh[cur][tid] * xu[cur][tid] : 0.f;
            cacc += 0.5f * part + pterm;
        }
        // x_next -> xu[nxt]
        if (tid < NS) {
            float acc = c1s[tid];
#pragma unroll
            for (int k = 0; k < NS; ++k) acc = fmaf(As[tid * 33 + k], xu[cur][k], acc);
#pragma unroll
            for (int k = 0; k < NC; ++k) acc = fmaf(Bs[tid * 17 + k], xu[cur][NS + k], acc);
            xu[nxt][tid] = acc;
        }
        cpwait0();
        __syncthreads();
    }

#pragma unroll
    for (int s = 16; s; s >>= 1) cacc += __shfl_xor_sync(0xffffffffu, cacc, s);
    if ((tid & 31) == 0) red[tid >> 5] = cacc;
    __syncthreads();
    if (tid == 0) {
        float tot = 0.f;
#pragma unroll
        for (int i = 0; i < 8; ++i) tot += red[i];
        out[cBase + b] = tot;
    }
}

// ---------------------------------------------------------------------------
extern "C" void kernel_launch(void* const* d_in, const int* in_sizes, int n_in,
                              void* d_out, int out_size)
{
    const float* x_init = (const float*)d_in[0];
    const float* Q      = (const float*)d_in[1];
    const float* p      = (const float*)d_in[2];
    const float* A      = (const float*)d_in[3];
    const float* Bm     = (const float*)d_in[4];
    const float* c1     = (const float*)d_in[5];
    float* out = (float*)d_out;

    lqr_bwd_kernel<<<NBATCH, 256>>>(Q, p, A, Bm, c1);
    lqr_fwd_kernel<<<NBATCH, 256>>>(Q, p, A, Bm, c1, x_init, out);
}